// round 16
// baseline (speedup 1.0000x reference)
#include <cuda_runtime.h>

// Problem constants
static const int BB  = 8;
static const int NN  = 20000;
static const int DD  = 64;
static const int DD2 = 128;
static const int RR  = 24;
static const int SS  = 3;
static const int EE  = 60000;
static const int KK  = 101;
static const int HL  = 50;
static const int FDIM = 192;   // D + 2D

// packed fp32x2 helpers (SASS FFMA2 path)
#define FMA_F32X2(d, a, b, c) \
    asm("fma.rn.f32x2 %0, %1, %2, %3;" : "=l"(d) : "l"(a), "l"(b), "l"(c))
#define PACKF2(d, lo, hi) \
    asm("mov.b64 %0, {%1, %2};" : "=l"(d) : "f"(lo), "f"(hi))
#define UNPACKF2(lo, hi, v) \
    asm("mov.b64 {%0, %1}, %2;" : "=f"(lo), "=f"(hi) : "l"(v))

// ---------------- scratch (device globals; no allocations allowed) ----------
__device__ float g_i [NN * DD];
__device__ float g_xA[NN * DD];
__device__ float g_xB[NN * DD];
__device__ int   g_cnt_poi[SS][NN];
__device__ int   g_cnt_dst[SS][NN];
__device__ int   g_rowstart[SS][NN];
__device__ int   g_rowfill[SS][NN];
__device__ int   g_total[SS];
__device__ int   g_csr_src[SS][EE];
__device__ int   g_csr_et[SS][EE];
__device__ float g_relsum[SS][2][NN * DD];
__device__ float g_query[BB * DD];
__device__ float g_xseq[BB * HL * DD2];
__device__ float g_qkv[BB * HL * 3 * DD2];
__device__ float g_ao[BB * HL * DD2];

// ---------------- CSR build (batched over all S snapshots) -------------------
__global__ void k_zero() {
    int s = blockIdx.y;
    int i = blockIdx.x * blockDim.x + threadIdx.x;
    if (i < NN) { g_cnt_poi[s][i] = 0; g_cnt_dst[s][i] = 0; g_rowfill[s][i] = 0; }
    if (i == 0) g_total[s] = 0;
}

__global__ void k_count(const int* __restrict__ src, const int* __restrict__ dst) {
    int s = blockIdx.y;
    int e = blockIdx.x * blockDim.x + threadIdx.x;
    if (e < EE) {
        atomicAdd(&g_cnt_poi[s][src[s * EE + e]], 1);
        atomicAdd(&g_cnt_poi[s][dst[s * EE + e]], 1);
        atomicAdd(&g_cnt_dst[s][dst[s * EE + e]], 1);
    }
}

__global__ void k_offsets() {
    int s = blockIdx.y;
    int n = blockIdx.x * blockDim.x + threadIdx.x;
    int lane = threadIdx.x & 31;
    int c = (n < NN) ? g_cnt_dst[s][n] : 0;
    int pre = c;
    #pragma unroll
    for (int off = 1; off < 32; off <<= 1) {
        int t = __shfl_up_sync(0xffffffffu, pre, off);
        if (lane >= off) pre += t;
    }
    int tot = __shfl_sync(0xffffffffu, pre, 31);
    int base = 0;
    if (lane == 31 && tot > 0) base = atomicAdd(&g_total[s], tot);
    base = __shfl_sync(0xffffffffu, base, 31);
    if (n < NN) g_rowstart[s][n] = base + pre - c;
}

__global__ void k_scatter(const int* __restrict__ src, const int* __restrict__ dst,
                          const int* __restrict__ et) {
    int s = blockIdx.y;
    int e = blockIdx.x * blockDim.x + threadIdx.x;
    if (e < EE) {
        int dn = dst[s * EE + e];
        int pos = g_rowstart[s][dn] + atomicAdd(&g_rowfill[s][dn], 1);
        g_csr_src[s][pos] = src[s * EE + e];
        g_csr_et[s][pos]  = et[s * EE + e];
    }
}

// relsum for all (s, layer) + snapshot-0 init + full query chain (extra block)
__global__ void k_relsum_init0(const float* __restrict__ rel,
                               const float* __restrict__ poi,
                               const float* __restrict__ qe,
                               const int* __restrict__ ridx,
                               const float* __restrict__ temb,
                               const int* __restrict__ gtime,
                               const float* __restrict__ lw,
                               const float* __restrict__ lb) {
    int s = blockIdx.y;
    int i = blockIdx.x * blockDim.x + threadIdx.x;  // NN*DD
    if (blockIdx.x == gridDim.x - 1) {
        if (s != 0) return;
        __shared__ float sq[BB * DD];
        int t = threadIdx.x;
        int b0 = t >> 6, d0 = t & 63;
        int t1 = t + 256;
        int b1 = t1 >> 6, d1 = t1 & 63;
        float q0 = qe[ridx[b0] * DD + d0];
        float q1 = qe[ridx[b1] * DD + d1];
        for (int ss2 = 0; ss2 < SS; ss2++) {
            int tt = gtime[ss2];
            sq[t]  = q0 + temb[tt * DD + d0];
            sq[t1] = q1 + temb[tt * DD + d1];
            __syncthreads();
            float a0 = lb[d0], a1 = lb[d1];
            #pragma unroll 8
            for (int k = 0; k < DD; k++) {
                a0 = fmaf(sq[b0 * DD + k], lw[k * DD + d0], a0);
                a1 = fmaf(sq[b1 * DD + k], lw[k * DD + d1], a1);
            }
            q0 = a0; q1 = a1;
            __syncthreads();
        }
        g_query[t] = q0;
        g_query[t1] = q1;
        return;
    }
    if (i >= NN * DD) return;
    int n = i >> 6, j = i & 63;
    int rs = g_rowstart[s][n], cnt = g_cnt_dst[s][n];
    float a0 = 0.f, a1 = 0.f;
    for (int p = rs; p < rs + cnt; p++) {
        int r = __ldg(&g_csr_et[s][p]);
        a0 += __ldg(&rel[r * DD + j]);
        a1 += __ldg(&rel[RR * DD + r * DD + j]);
    }
    g_relsum[s][0][i] = a0;
    g_relsum[s][1][i] = a1;
    if (s == 0) g_i[i] = (float)g_cnt_poi[0][n] * poi[i];
}

// ---------------- scalar GNN layer (modes as R13) -----------------------------
__global__ void k_layer(int s, int layer, int mode,
                        const float* __restrict__ W,
                        const float* __restrict__ bias,
                        const float* __restrict__ gW,
                        const float* __restrict__ gb,
                        const float* __restrict__ poi) {
    const int P = 20;
    __shared__ float s_in[2 * DD * P];
    int n0 = blockIdx.x * 16;
    int tid = threadIdx.x;
    int j = tid & 63, gbk = tid >> 6;
    const float* xin  = (layer == 0) ? g_i : g_xA;
    const float* relsum = g_relsum[s][layer];
    const int* csr = g_csr_src[s];
    #pragma unroll
    for (int gi = 0; gi < 4; gi++) {
        int g = gbk * 4 + gi;
        int n = n0 + g;
        int rs = g_rowstart[s][n], cnt = g_cnt_dst[s][n];
        float acc = __ldg(&relsum[n * DD + j]);
        for (int p = rs; p < rs + cnt; p++)
            acc += xin[__ldg(&csr[p]) * DD + j];
        s_in[j * P + g] = acc;
        s_in[(DD + j) * P + g] = g_i[n * DD + j];
    }
    __syncthreads();
    float bj = bias[j];
    unsigned long long acc01, acc23;
    PACKF2(acc01, bj, bj);
    acc23 = acc01;
    #pragma unroll 8
    for (int k = 0; k < 2 * DD; k++) {
        float w = __ldg(&W[k * DD + j]);
        unsigned long long wd;
        PACKF2(wd, w, w);
        ulonglong2 x = *reinterpret_cast<const ulonglong2*>(&s_in[k * P + gbk * 4]);
        FMA_F32X2(acc01, wd, x.x, acc01);
        FMA_F32X2(acc23, wd, x.y, acc23);
    }
    float accs[4];
    UNPACKF2(accs[0], accs[1], acc01);
    UNPACKF2(accs[2], accs[3], acc23);
    #pragma unroll
    for (int gi = 0; gi < 4; gi++) accs[gi] = fmaxf(accs[gi], 0.f);

    if (mode == 0) {
        #pragma unroll
        for (int gi = 0; gi < 4; gi++)
            g_xA[(n0 + gbk * 4 + gi) * DD + j] = accs[gi];
        return;
    }
    if (mode == 1) {
        #pragma unroll
        for (int gi = 0; gi < 4; gi++)
            g_xB[(n0 + gbk * 4 + gi) * DD + j] = accs[gi];
        return;
    }
    __syncthreads();
    #pragma unroll
    for (int gi = 0; gi < 4; gi++)
        s_in[j * P + gbk * 4 + gi] = accs[gi];
    __syncthreads();
    float gbj = gb[j];
    unsigned long long ga01, ga23;
    PACKF2(ga01, gbj, gbj);
    ga23 = ga01;
    #pragma unroll 8
    for (int k = 0; k < DD; k++) {
        float w = __ldg(&gW[k * DD + j]);
        unsigned long long wd;
        PACKF2(wd, w, w);
        ulonglong2 x = *reinterpret_cast<const ulonglong2*>(&s_in[k * P + gbk * 4]);
        FMA_F32X2(ga01, wd, x.x, ga01);
        FMA_F32X2(ga23, wd, x.y, ga23);
    }
    float gl[4];
    UNPACKF2(gl[0], gl[1], ga01);
    UNPACKF2(gl[2], gl[3], ga23);
    int sn = s + 1;
    #pragma unroll
    for (int gi = 0; gi < 4; gi++) {
        int g = gbk * 4 + gi;
        int n = n0 + g;
        float gt = 1.f / (1.f + __expf(-gl[gi]));
        float prv = s_in[j * P + g];
        float ione = (float)g_cnt_poi[sn][n] * poi[n * DD + j];
        g_i[n * DD + j] = ione * gt + (1.f - gt) * prv;
    }
}

// ---------------- transformer: qkv, 2 rows per block --------------------------
__global__ void k_qkv(const float* __restrict__ Wqkv, int l,
                      int doXseq, const int* __restrict__ hp,
                      const float* __restrict__ hte) {
    __shared__ float sxp[DD2 * 2];       // [k][r], r=0,1
    int row0 = blockIdx.x * 2;
    int c = threadIdx.x;                 // 384
    if (c < DD2) {
        #pragma unroll
        for (int r = 0; r < 2; r++) {
            int row = row0 + r;
            float v;
            if (doXseq) {
                int b = row / HL;
                int p = hp[row];
                v = (c < DD) ? g_xB[p * DD + c] : g_query[b * DD + (c - DD)];
                v += hte[row * DD2 + c];
                g_xseq[row * DD2 + c] = v;
            } else {
                v = g_xseq[row * DD2 + c];
            }
            sxp[c * 2 + r] = v;
        }
    }
    __syncthreads();
    const float* W = Wqkv + l * DD2 * 3 * DD2;
    unsigned long long acc;
    {
        float z = 0.f;
        PACKF2(acc, z, z);
    }
    #pragma unroll 8
    for (int k = 0; k < DD2; k++) {
        float w = __ldg(&W[k * 384 + c]);
        unsigned long long wd, x;
        PACKF2(wd, w, w);
        x = *reinterpret_cast<const unsigned long long*>(&sxp[k * 2]);
        FMA_F32X2(acc, wd, x, acc);
    }
    float lo, hi;
    UNPACKF2(lo, hi, acc);
    g_qkv[row0 * 384 + c] = lo;
    g_qkv[(row0 + 1) * 384 + c] = hi;
}

__global__ void k_att() {
    const int PQ = 65;
    __shared__ float sq[HL * PQ];
    __shared__ float sk[HL * PQ];
    __shared__ float sv[HL * PQ];
    __shared__ float ss[HL * HL];
    int b = blockIdx.x, h = blockIdx.y;
    int tid = threadIdx.x;           // 256
    for (int i = tid; i < HL * DD; i += 256) {
        int t = i / DD, d = i & 63;
        int base = (b * HL + t) * 384 + h * 64 + d;
        sq[t * PQ + d] = g_qkv[base];
        sk[t * PQ + d] = g_qkv[base + 128];
        sv[t * PQ + d] = g_qkv[base + 256];
    }
    __syncthreads();
    for (int o = tid; o < HL * HL; o += 256) {
        int i = o / HL, jj = o % HL;
        float acc = 0.f;
        #pragma unroll 8
        for (int d = 0; d < 64; d++) acc = fmaf(sq[i * PQ + d], sk[jj * PQ + d], acc);
        ss[o] = acc * 0.125f;
    }
    __syncthreads();
    for (int i = tid; i < HL; i += 256) {
        float m = -1e30f;
        for (int jj = 0; jj < HL; jj++) m = fmaxf(m, ss[i * HL + jj]);
        float sum = 0.f;
        for (int jj = 0; jj < HL; jj++) { float e = __expf(ss[i * HL + jj] - m); ss[i * HL + jj] = e; sum += e; }
        float inv = 1.f / sum;
        for (int jj = 0; jj < HL; jj++) ss[i * HL + jj] *= inv;
    }
    __syncthreads();
    for (int o = tid; o < HL * DD; o += 256) {
        int i = o / DD, d = o & 63;
        float acc = 0.f;
        #pragma unroll 5
        for (int jj = 0; jj < HL; jj++) acc = fmaf(ss[i * HL + jj], sv[jj * PQ + d], acc);
        g_ao[(b * HL + i) * DD2 + h * 64 + d] = acc;
    }
}

// ---- fused proj + LN1 + FF1 + FF2 + LN2 : 8 rows per block, 128 threads -----
__global__ void k_ffn(const float* __restrict__ Wo, const float* __restrict__ ln1,
                      const float* __restrict__ W1, const float* __restrict__ b1,
                      const float* __restrict__ W2, const float* __restrict__ b2,
                      const float* __restrict__ ln2, int l) {
    const int R = 8;
    __shared__ float sao[DD2 * R];       // [k][r] : attention-out, then reused? keep
    __shared__ float xsp[DD2 * R];       // [k][r] : ln1 output
    __shared__ float shf[512 * R];       // [k][r] : ff1 relu output (16 KB)
    __shared__ float red[R * DD2];
    int row0 = blockIdx.x * R;
    int j = threadIdx.x;                 // 128
    #pragma unroll
    for (int r = 0; r < R; r++) sao[j * R + r] = g_ao[(row0 + r) * DD2 + j];
    __syncthreads();
    // ---- attention out-projection (8 rows) ----
    const float* W = Wo + l * DD2 * DD2;
    unsigned long long pacc[4];
    {
        float z = 0.f;
        PACKF2(pacc[0], z, z);
        pacc[1] = pacc[0]; pacc[2] = pacc[0]; pacc[3] = pacc[0];
    }
    #pragma unroll 4
    for (int k = 0; k < DD2; k++) {
        float w = __ldg(&W[k * DD2 + j]);
        unsigned long long wd;
        PACKF2(wd, w, w);
        ulonglong2 x0 = *(const ulonglong2*)&sao[k * R];
        ulonglong2 x1 = *(const ulonglong2*)&sao[k * R + 4];
        FMA_F32X2(pacc[0], wd, x0.x, pacc[0]);
        FMA_F32X2(pacc[1], wd, x0.y, pacc[1]);
        FMA_F32X2(pacc[2], wd, x1.x, pacc[2]);
        FMA_F32X2(pacc[3], wd, x1.y, pacc[3]);
    }
    float v[R];
    #pragma unroll
    for (int q = 0; q < 4; q++) UNPACKF2(v[2 * q], v[2 * q + 1], pacc[q]);
    #pragma unroll
    for (int r = 0; r < R; r++) v[r] += g_xseq[(row0 + r) * DD2 + j];
    // ---- LN1 (8 rows in parallel) ----
    #pragma unroll
    for (int r = 0; r < R; r++) red[r * DD2 + j] = v[r];
    __syncthreads();
    for (int off = 64; off > 0; off >>= 1) {
        if (j < off)
            #pragma unroll
            for (int r = 0; r < R; r++) red[r * DD2 + j] += red[r * DD2 + j + off];
        __syncthreads();
    }
    float mean[R];
    #pragma unroll
    for (int r = 0; r < R; r++) mean[r] = red[r * DD2] * (1.f / 128.f);
    __syncthreads();
    float dv[R];
    #pragma unroll
    for (int r = 0; r < R; r++) { dv[r] = v[r] - mean[r]; red[r * DD2 + j] = dv[r] * dv[r]; }
    __syncthreads();
    for (int off = 64; off > 0; off >>= 1) {
        if (j < off)
            #pragma unroll
            for (int r = 0; r < R; r++) red[r * DD2 + j] += red[r * DD2 + j + off];
        __syncthreads();
    }
    const float* ln1l = ln1 + l * 2 * DD2;
    float lnw = ln1l[j], lnb = ln1l[DD2 + j];
    float xv[R];
    #pragma unroll
    for (int r = 0; r < R; r++) {
        float var = red[r * DD2] * (1.f / 128.f);
        xv[r] = dv[r] * rsqrtf(var + 1e-5f) * lnw + lnb;
        xsp[j * R + r] = xv[r];
    }
    __syncthreads();
    // ---- FF1: thread j -> cols j*4..j*4+3, 8 rows ----
    const float* W1l = W1 + l * DD2 * 512;
    float4 b14 = __ldg((const float4*)&b1[l * 512 + j * 4]);
    unsigned long long f1[4][4];         // [col][rowpair]
    {
        float bb[4] = {b14.x, b14.y, b14.z, b14.w};
        #pragma unroll
        for (int c = 0; c < 4; c++) {
            unsigned long long p;
            PACKF2(p, bb[c], bb[c]);
            f1[c][0] = p; f1[c][1] = p; f1[c][2] = p; f1[c][3] = p;
        }
    }
    #pragma unroll 2
    for (int k = 0; k < DD2; k++) {
        float4 w4 = __ldg((const float4*)&W1l[k * 512 + j * 4]);
        ulonglong2 x0 = *(const ulonglong2*)&xsp[k * R];
        ulonglong2 x1 = *(const ulonglong2*)&xsp[k * R + 4];
        float wc[4] = {w4.x, w4.y, w4.z, w4.w};
        #pragma unroll
        for (int c = 0; c < 4; c++) {
            unsigned long long wd;
            PACKF2(wd, wc[c], wc[c]);
            FMA_F32X2(f1[c][0], wd, x0.x, f1[c][0]);
            FMA_F32X2(f1[c][1], wd, x0.y, f1[c][1]);
            FMA_F32X2(f1[c][2], wd, x1.x, f1[c][2]);
            FMA_F32X2(f1[c][3], wd, x1.y, f1[c][3]);
        }
    }
    #pragma unroll
    for (int c = 0; c < 4; c++) {
        #pragma unroll
        for (int q = 0; q < 4; q++) {
            float lo, hi;
            UNPACKF2(lo, hi, f1[c][q]);
            shf[(j * 4 + c) * R + 2 * q]     = fmaxf(lo, 0.f);
            shf[(j * 4 + c) * R + 2 * q + 1] = fmaxf(hi, 0.f);
        }
    }
    __syncthreads();
    // ---- FF2 ----
    const float* W2l = W2 + l * 512 * DD2;
    float bb2 = b2[l * DD2 + j];
    unsigned long long f2[4];
    {
        unsigned long long p;
        PACKF2(p, bb2, bb2);
        f2[0] = p; f2[1] = p; f2[2] = p; f2[3] = p;
    }
    #pragma unroll 4
    for (int k = 0; k < 512; k++) {
        float w = __ldg(&W2l[k * DD2 + j]);
        unsigned long long wd;
        PACKF2(wd, w, w);
        ulonglong2 y0 = *(const ulonglong2*)&shf[k * R];
        ulonglong2 y1 = *(const ulonglong2*)&shf[k * R + 4];
        FMA_F32X2(f2[0], wd, y0.x, f2[0]);
        FMA_F32X2(f2[1], wd, y0.y, f2[1]);
        FMA_F32X2(f2[2], wd, y1.x, f2[2]);
        FMA_F32X2(f2[3], wd, y1.y, f2[3]);
    }
    float v2[R];
    #pragma unroll
    for (int q = 0; q < 4; q++) UNPACKF2(v2[2 * q], v2[2 * q + 1], f2[q]);
    #pragma unroll
    for (int r = 0; r < R; r++) v2[r] += xv[r];
    // ---- LN2 ----
    #pragma unroll
    for (int r = 0; r < R; r++) red[r * DD2 + j] = v2[r];
    __syncthreads();
    for (int off = 64; off > 0; off >>= 1) {
        if (j < off)
            #pragma unroll
            for (int r = 0; r < R; r++) red[r * DD2 + j] += red[r * DD2 + j + off];
        __syncthreads();
    }
    float mean2[R];
    #pragma unroll
    for (int r = 0; r < R; r++) mean2[r] = red[r * DD2] * (1.f / 128.f);
    __syncthreads();
    float dv2[R];
    #pragma unroll
    for (int r = 0; r < R; r++) { dv2[r] = v2[r] - mean2[r]; red[r * DD2 + j] = dv2[r] * dv2[r]; }
    __syncthreads();
    for (int off = 64; off > 0; off >>= 1) {
        if (j < off)
            #pragma unroll
            for (int r = 0; r < R; r++) red[r * DD2 + j] += red[r * DD2 + j + off];
        __syncthreads();
    }
    const float* ln2l = ln2 + l * 2 * DD2;
    float lnw2 = ln2l[j], lnb2 = ln2l[DD2 + j];
    #pragma unroll
    for (int r = 0; r < R; r++) {
        float var2 = red[r * DD2] * (1.f / 128.f);
        g_xseq[(row0 + r) * DD2 + j] = dv2[r] * rsqrtf(var2 + 1e-5f) * lnw2 + lnb2;
    }
}

// ---------------- final scoring MLP: 4 candidates per block -------------------
__global__ void k_score(const int* __restrict__ tidx,
                        const float* __restrict__ W1, const float* __restrict__ b1,
                        const float* __restrict__ W2, const float* __restrict__ b2,
                        float* __restrict__ out) {
    const int C = 4;
    __shared__ float ftp[FDIM * C];      // [q][cand]
    __shared__ float sh[C][256];
    int g0 = blockIdx.x * C;
    int j = threadIdx.x;                 // 192
    #pragma unroll
    for (int c = 0; c < C; c++) {
        int gc = g0 + c;
        int b = gc / KK;
        float v;
        if (j < DD) {
            v = g_xB[tidx[gc] * DD + j];
        } else {
            int col = j - DD;
            float ssum = 0.f;
            #pragma unroll 10
            for (int t = 0; t < HL; t++) ssum += g_xseq[(b * HL + t) * DD2 + col];
            v = ssum * (1.f / (float)HL);
        }
        ftp[j * C + c] = v;
    }
    if (j < 64) {
        #pragma unroll
        for (int c = 0; c < C; c++) sh[c][192 + j] = 0.f;
    }
    __syncthreads();
    float bj = b1[j];
    unsigned long long a01, a23;
    PACKF2(a01, bj, bj);
    a23 = a01;
    #pragma unroll 8
    for (int q = 0; q < FDIM; q++) {
        float w = __ldg(&W1[q * FDIM + j]);
        unsigned long long wd;
        PACKF2(wd, w, w);
        ulonglong2 x = *(const ulonglong2*)&ftp[q * C];
        FMA_F32X2(a01, wd, x.x, a01);
        FMA_F32X2(a23, wd, x.y, a23);
    }
    float h[4];
    UNPACKF2(h[0], h[1], a01);
    UNPACKF2(h[2], h[3], a23);
    float w2j = W2[j];
    #pragma unroll
    for (int c = 0; c < C; c++) sh[c][j] = fmaxf(h[c], 0.f) * w2j;
    __syncthreads();
    for (int off = 128; off > 0; off >>= 1) {
        if (j < off) {
            #pragma unroll
            for (int c = 0; c < C; c++) sh[c][j] += sh[c][j + off];
        }
        __syncthreads();
    }
    if (j < C) out[g0 + j] = sh[j][0] + b2[0];
}

// ---------------- host launcher -------------------------------------------------
extern "C" void kernel_launch(void* const* d_in, const int* in_sizes, int n_in,
                              void* d_out, int out_size) {
    const float* poi   = (const float*)d_in[0];
    const float* qemb  = (const float*)d_in[1];
    const float* gateW = (const float*)d_in[2];
    const float* gateb = (const float*)d_in[3];
    const float* gnn_rel = (const float*)d_in[4];
    const float* gnn_W   = (const float*)d_in[5];
    const float* gnn_b   = (const float*)d_in[6];
    const float* gte  = (const float*)d_in[7];
    const float* glW  = (const float*)d_in[8];
    const float* glb  = (const float*)d_in[9];
    const float* Wqkv = (const float*)d_in[10];
    const float* Wo   = (const float*)d_in[11];
    const float* ln1  = (const float*)d_in[12];
    const float *W1, *b1, *W2, *b2, *ln2;
    if (in_sizes[13] == 2 * 2 * DD2) {       // dict order: ln2 right after ln1
        ln2 = (const float*)d_in[13];
        W1  = (const float*)d_in[14];
        b1  = (const float*)d_in[15];
        W2  = (const float*)d_in[16];
        b2  = (const float*)d_in[17];
    } else {                                 // signature order
        W1  = (const float*)d_in[13];
        b1  = (const float*)d_in[14];
        W2  = (const float*)d_in[15];
        b2  = (const float*)d_in[16];
        ln2 = (const float*)d_in[17];
    }
    const float* mW1 = (const float*)d_in[18];
    const float* mb1 = (const float*)d_in[19];
    const float* mW2 = (const float*)d_in[20];
    const float* mb2 = (const float*)d_in[21];
    const float* hte = (const float*)d_in[22];
    const int* esrc  = (const int*)d_in[23];
    const int* edst  = (const int*)d_in[24];
    const int* etyp  = (const int*)d_in[25];
    const int* ridx  = (const int*)d_in[27];
    const int* tidx  = (const int*)d_in[28];
    const int* hpoi  = (const int*)d_in[29];
    const int* gtime = (const int*)d_in[30];
    float* out = (float*)d_out;

    k_zero<<<dim3((NN + 255) / 256, SS), 256>>>();
    k_count<<<dim3((EE + 255) / 256, SS), 256>>>(esrc, edst);
    k_offsets<<<dim3((NN + 255) / 256, SS), 256>>>();
    k_scatter<<<dim3((EE + 255) / 256, SS), 256>>>(esrc, edst, etyp);
    k_relsum_init0<<<dim3(NN * DD / 256 + 1, SS), 256>>>(
        gnn_rel, poi, qemb, ridx, gte, gtime, glW, glb);

    for (int s = 0; s < SS; s++) {
        k_layer<<<NN / 16, 256>>>(s, 0, 0, gnn_W, gnn_b, gateW, gateb, poi);
        int mode = (s < SS - 1) ? 2 : 1;
        k_layer<<<NN / 16, 256>>>(s, 1, mode, gnn_W + 2 * DD * DD, gnn_b + DD,
                                  gateW, gateb, poi);
    }

    for (int l = 0; l < 2; l++) {
        k_qkv<<<BB * HL / 2, 3 * DD2>>>(Wqkv, l, l == 0 ? 1 : 0, hpoi, hte);
        k_att<<<dim3(BB, 2), 256>>>();
        k_ffn<<<BB * HL / 8, DD2>>>(Wo, ln1, W1, b1, W2, b2, ln2, l);
    }
    k_score<<<BB * KK / 4, FDIM>>>(tidx, mW1, mb1, mW2, mb2, out);
}

// round 17
// speedup vs baseline: 1.0052x; 1.0052x over previous
#include <cuda_runtime.h>

// Problem constants
static const int BB  = 8;
static const int NN  = 20000;
static const int DD  = 64;
static const int DD2 = 128;
static const int RR  = 24;
static const int SS  = 3;
static const int EE  = 60000;
static const int KK  = 101;
static const int HL  = 50;
static const int FDIM = 192;   // D + 2D

// packed fp32x2 helpers (SASS FFMA2 path)
#define FMA_F32X2(d, a, b, c) \
    asm("fma.rn.f32x2 %0, %1, %2, %3;" : "=l"(d) : "l"(a), "l"(b), "l"(c))
#define PACKF2(d, lo, hi) \
    asm("mov.b64 %0, {%1, %2};" : "=l"(d) : "f"(lo), "f"(hi))
#define UNPACKF2(lo, hi, v) \
    asm("mov.b64 {%0, %1}, %2;" : "=f"(lo), "=f"(hi) : "l"(v))

// ---------------- scratch (device globals; no allocations allowed) ----------
__device__ float g_i [NN * DD];
__device__ float g_xA[NN * DD];
__device__ float g_xB[NN * DD];
__device__ int   g_cnt_poi[SS][NN];
__device__ int   g_cnt_dst[SS][NN];
__device__ int   g_rowstart[SS][NN];
__device__ int   g_rowfill[SS][NN];
__device__ int   g_total[SS];
__device__ int   g_csr_src[SS][EE];
__device__ int   g_csr_et[SS][EE];
__device__ float g_relsum[SS][2][NN * DD];
__device__ float g_query[BB * DD];
__device__ float g_xseq[BB * HL * DD2];
__device__ float g_qkv[BB * HL * 3 * DD2];
__device__ float g_ao[BB * HL * DD2];

// ---------------- CSR build (batched over all S snapshots) -------------------
__global__ void k_zero() {
    int s = blockIdx.y;
    int i = blockIdx.x * blockDim.x + threadIdx.x;
    if (i < NN) { g_cnt_poi[s][i] = 0; g_cnt_dst[s][i] = 0; g_rowfill[s][i] = 0; }
    if (i == 0) g_total[s] = 0;
}

__global__ void k_count(const int* __restrict__ src, const int* __restrict__ dst) {
    int s = blockIdx.y;
    int e = blockIdx.x * blockDim.x + threadIdx.x;
    if (e < EE) {
        atomicAdd(&g_cnt_poi[s][src[s * EE + e]], 1);
        atomicAdd(&g_cnt_poi[s][dst[s * EE + e]], 1);
        atomicAdd(&g_cnt_dst[s][dst[s * EE + e]], 1);
    }
}

__global__ void k_offsets() {
    int s = blockIdx.y;
    int n = blockIdx.x * blockDim.x + threadIdx.x;
    int lane = threadIdx.x & 31;
    int c = (n < NN) ? g_cnt_dst[s][n] : 0;
    int pre = c;
    #pragma unroll
    for (int off = 1; off < 32; off <<= 1) {
        int t = __shfl_up_sync(0xffffffffu, pre, off);
        if (lane >= off) pre += t;
    }
    int tot = __shfl_sync(0xffffffffu, pre, 31);
    int base = 0;
    if (lane == 31 && tot > 0) base = atomicAdd(&g_total[s], tot);
    base = __shfl_sync(0xffffffffu, base, 31);
    if (n < NN) g_rowstart[s][n] = base + pre - c;
}

__global__ void k_scatter(const int* __restrict__ src, const int* __restrict__ dst,
                          const int* __restrict__ et) {
    int s = blockIdx.y;
    int e = blockIdx.x * blockDim.x + threadIdx.x;
    if (e < EE) {
        int dn = dst[s * EE + e];
        int pos = g_rowstart[s][dn] + atomicAdd(&g_rowfill[s][dn], 1);
        g_csr_src[s][pos] = src[s * EE + e];
        g_csr_et[s][pos]  = et[s * EE + e];
    }
}

// relsum for all (s, layer) + snapshot-0 init + full query chain (extra block)
__global__ void k_relsum_init0(const float* __restrict__ rel,
                               const float* __restrict__ poi,
                               const float* __restrict__ qe,
                               const int* __restrict__ ridx,
                               const float* __restrict__ temb,
                               const int* __restrict__ gtime,
                               const float* __restrict__ lw,
                               const float* __restrict__ lb) {
    int s = blockIdx.y;
    int i = blockIdx.x * blockDim.x + threadIdx.x;  // NN*DD
    if (blockIdx.x == gridDim.x - 1) {
        if (s != 0) return;
        __shared__ float sq[BB * DD];
        int t = threadIdx.x;
        int b0 = t >> 6, d0 = t & 63;
        int t1 = t + 256;
        int b1 = t1 >> 6, d1 = t1 & 63;
        float q0 = qe[ridx[b0] * DD + d0];
        float q1 = qe[ridx[b1] * DD + d1];
        for (int ss2 = 0; ss2 < SS; ss2++) {
            int tt = gtime[ss2];
            sq[t]  = q0 + temb[tt * DD + d0];
            sq[t1] = q1 + temb[tt * DD + d1];
            __syncthreads();
            float a0 = lb[d0], a1 = lb[d1];
            #pragma unroll 8
            for (int k = 0; k < DD; k++) {
                a0 = fmaf(sq[b0 * DD + k], lw[k * DD + d0], a0);
                a1 = fmaf(sq[b1 * DD + k], lw[k * DD + d1], a1);
            }
            q0 = a0; q1 = a1;
            __syncthreads();
        }
        g_query[t] = q0;
        g_query[t1] = q1;
        return;
    }
    if (i >= NN * DD) return;
    int n = i >> 6, j = i & 63;
    int rs = g_rowstart[s][n], cnt = g_cnt_dst[s][n];
    float a0 = 0.f, a1 = 0.f;
    for (int p = rs; p < rs + cnt; p++) {
        int r = __ldg(&g_csr_et[s][p]);
        a0 += __ldg(&rel[r * DD + j]);
        a1 += __ldg(&rel[RR * DD + r * DD + j]);
    }
    g_relsum[s][0][i] = a0;
    g_relsum[s][1][i] = a1;
    if (s == 0) g_i[i] = (float)g_cnt_poi[0][n] * poi[i];
}

// ---------------- scalar GNN layer (modes as R13) -----------------------------
__global__ void k_layer(int s, int layer, int mode,
                        const float* __restrict__ W,
                        const float* __restrict__ bias,
                        const float* __restrict__ gW,
                        const float* __restrict__ gb,
                        const float* __restrict__ poi) {
    const int P = 20;
    __shared__ float s_in[2 * DD * P];
    int n0 = blockIdx.x * 16;
    int tid = threadIdx.x;
    int j = tid & 63, gbk = tid >> 6;
    const float* xin  = (layer == 0) ? g_i : g_xA;
    const float* relsum = g_relsum[s][layer];
    const int* csr = g_csr_src[s];
    #pragma unroll
    for (int gi = 0; gi < 4; gi++) {
        int g = gbk * 4 + gi;
        int n = n0 + g;
        int rs = g_rowstart[s][n], cnt = g_cnt_dst[s][n];
        float acc = __ldg(&relsum[n * DD + j]);
        for (int p = rs; p < rs + cnt; p++)
            acc += xin[__ldg(&csr[p]) * DD + j];
        s_in[j * P + g] = acc;
        s_in[(DD + j) * P + g] = g_i[n * DD + j];
    }
    __syncthreads();
    float bj = bias[j];
    unsigned long long acc01, acc23;
    PACKF2(acc01, bj, bj);
    acc23 = acc01;
    #pragma unroll 8
    for (int k = 0; k < 2 * DD; k++) {
        float w = __ldg(&W[k * DD + j]);
        unsigned long long wd;
        PACKF2(wd, w, w);
        ulonglong2 x = *reinterpret_cast<const ulonglong2*>(&s_in[k * P + gbk * 4]);
        FMA_F32X2(acc01, wd, x.x, acc01);
        FMA_F32X2(acc23, wd, x.y, acc23);
    }
    float accs[4];
    UNPACKF2(accs[0], accs[1], acc01);
    UNPACKF2(accs[2], accs[3], acc23);
    #pragma unroll
    for (int gi = 0; gi < 4; gi++) accs[gi] = fmaxf(accs[gi], 0.f);

    if (mode == 0) {
        #pragma unroll
        for (int gi = 0; gi < 4; gi++)
            g_xA[(n0 + gbk * 4 + gi) * DD + j] = accs[gi];
        return;
    }
    if (mode == 1) {
        #pragma unroll
        for (int gi = 0; gi < 4; gi++)
            g_xB[(n0 + gbk * 4 + gi) * DD + j] = accs[gi];
        return;
    }
    __syncthreads();
    #pragma unroll
    for (int gi = 0; gi < 4; gi++)
        s_in[j * P + gbk * 4 + gi] = accs[gi];
    __syncthreads();
    float gbj = gb[j];
    unsigned long long ga01, ga23;
    PACKF2(ga01, gbj, gbj);
    ga23 = ga01;
    #pragma unroll 8
    for (int k = 0; k < DD; k++) {
        float w = __ldg(&gW[k * DD + j]);
        unsigned long long wd;
        PACKF2(wd, w, w);
        ulonglong2 x = *reinterpret_cast<const ulonglong2*>(&s_in[k * P + gbk * 4]);
        FMA_F32X2(ga01, wd, x.x, ga01);
        FMA_F32X2(ga23, wd, x.y, ga23);
    }
    float gl[4];
    UNPACKF2(gl[0], gl[1], ga01);
    UNPACKF2(gl[2], gl[3], ga23);
    int sn = s + 1;
    #pragma unroll
    for (int gi = 0; gi < 4; gi++) {
        int g = gbk * 4 + gi;
        int n = n0 + g;
        float gt = 1.f / (1.f + __expf(-gl[gi]));
        float prv = s_in[j * P + g];
        float ione = (float)g_cnt_poi[sn][n] * poi[n * DD + j];
        g_i[n * DD + j] = ione * gt + (1.f - gt) * prv;
    }
}

// ---------------- transformer: qkv, 2 rows per block --------------------------
__global__ void k_qkv(const float* __restrict__ Wqkv, int l,
                      int doXseq, const int* __restrict__ hp,
                      const float* __restrict__ hte) {
    __shared__ float sxp[DD2 * 2];       // [k][r], r=0,1
    int row0 = blockIdx.x * 2;
    int c = threadIdx.x;                 // 384
    if (c < DD2) {
        #pragma unroll
        for (int r = 0; r < 2; r++) {
            int row = row0 + r;
            float v;
            if (doXseq) {
                int b = row / HL;
                int p = hp[row];
                v = (c < DD) ? g_xB[p * DD + c] : g_query[b * DD + (c - DD)];
                v += hte[row * DD2 + c];
                g_xseq[row * DD2 + c] = v;
            } else {
                v = g_xseq[row * DD2 + c];
            }
            sxp[c * 2 + r] = v;
        }
    }
    __syncthreads();
    const float* W = Wqkv + l * DD2 * 3 * DD2;
    unsigned long long acc;
    {
        float z = 0.f;
        PACKF2(acc, z, z);
    }
    #pragma unroll 8
    for (int k = 0; k < DD2; k++) {
        float w = __ldg(&W[k * 384 + c]);
        unsigned long long wd, x;
        PACKF2(wd, w, w);
        x = *reinterpret_cast<const unsigned long long*>(&sxp[k * 2]);
        FMA_F32X2(acc, wd, x, acc);
    }
    float lo, hi;
    UNPACKF2(lo, hi, acc);
    g_qkv[row0 * 384 + c] = lo;
    g_qkv[(row0 + 1) * 384 + c] = hi;
}

__global__ void k_att() {
    const int PQ = 65;
    __shared__ float sq[HL * PQ];
    __shared__ float sk[HL * PQ];
    __shared__ float sv[HL * PQ];
    __shared__ float ss[HL * HL];
    int b = blockIdx.x, h = blockIdx.y;
    int tid = threadIdx.x;           // 256
    for (int i = tid; i < HL * DD; i += 256) {
        int t = i / DD, d = i & 63;
        int base = (b * HL + t) * 384 + h * 64 + d;
        sq[t * PQ + d] = g_qkv[base];
        sk[t * PQ + d] = g_qkv[base + 128];
        sv[t * PQ + d] = g_qkv[base + 256];
    }
    __syncthreads();
    for (int o = tid; o < HL * HL; o += 256) {
        int i = o / HL, jj = o % HL;
        float acc = 0.f;
        #pragma unroll 8
        for (int d = 0; d < 64; d++) acc = fmaf(sq[i * PQ + d], sk[jj * PQ + d], acc);
        ss[o] = acc * 0.125f;
    }
    __syncthreads();
    for (int i = tid; i < HL; i += 256) {
        float m = -1e30f;
        for (int jj = 0; jj < HL; jj++) m = fmaxf(m, ss[i * HL + jj]);
        float sum = 0.f;
        for (int jj = 0; jj < HL; jj++) { float e = __expf(ss[i * HL + jj] - m); ss[i * HL + jj] = e; sum += e; }
        float inv = 1.f / sum;
        for (int jj = 0; jj < HL; jj++) ss[i * HL + jj] *= inv;
    }
    __syncthreads();
    for (int o = tid; o < HL * DD; o += 256) {
        int i = o / DD, d = o & 63;
        float acc = 0.f;
        #pragma unroll 5
        for (int jj = 0; jj < HL; jj++) acc = fmaf(ss[i * HL + jj], sv[jj * PQ + d], acc);
        g_ao[(b * HL + i) * DD2 + h * 64 + d] = acc;
    }
}

// ---- fused proj + LN1 + FF1 + FF2 + LN2 : 8 rows per block, 128 threads -----
__global__ void k_ffn(const float* __restrict__ Wo, const float* __restrict__ ln1,
                      const float* __restrict__ W1, const float* __restrict__ b1,
                      const float* __restrict__ W2, const float* __restrict__ b2,
                      const float* __restrict__ ln2, int l) {
    const int R = 8;
    __shared__ float sao[DD2 * R];       // [k][r] : attention-out, then reused? keep
    __shared__ float xsp[DD2 * R];       // [k][r] : ln1 output
    __shared__ float shf[512 * R];       // [k][r] : ff1 relu output (16 KB)
    __shared__ float red[R * DD2];
    int row0 = blockIdx.x * R;
    int j = threadIdx.x;                 // 128
    #pragma unroll
    for (int r = 0; r < R; r++) sao[j * R + r] = g_ao[(row0 + r) * DD2 + j];
    __syncthreads();
    // ---- attention out-projection (8 rows) ----
    const float* W = Wo + l * DD2 * DD2;
    unsigned long long pacc[4];
    {
        float z = 0.f;
        PACKF2(pacc[0], z, z);
        pacc[1] = pacc[0]; pacc[2] = pacc[0]; pacc[3] = pacc[0];
    }
    #pragma unroll 4
    for (int k = 0; k < DD2; k++) {
        float w = __ldg(&W[k * DD2 + j]);
        unsigned long long wd;
        PACKF2(wd, w, w);
        ulonglong2 x0 = *(const ulonglong2*)&sao[k * R];
        ulonglong2 x1 = *(const ulonglong2*)&sao[k * R + 4];
        FMA_F32X2(pacc[0], wd, x0.x, pacc[0]);
        FMA_F32X2(pacc[1], wd, x0.y, pacc[1]);
        FMA_F32X2(pacc[2], wd, x1.x, pacc[2]);
        FMA_F32X2(pacc[3], wd, x1.y, pacc[3]);
    }
    float v[R];
    #pragma unroll
    for (int q = 0; q < 4; q++) UNPACKF2(v[2 * q], v[2 * q + 1], pacc[q]);
    #pragma unroll
    for (int r = 0; r < R; r++) v[r] += g_xseq[(row0 + r) * DD2 + j];
    // ---- LN1 (8 rows in parallel) ----
    #pragma unroll
    for (int r = 0; r < R; r++) red[r * DD2 + j] = v[r];
    __syncthreads();
    for (int off = 64; off > 0; off >>= 1) {
        if (j < off)
            #pragma unroll
            for (int r = 0; r < R; r++) red[r * DD2 + j] += red[r * DD2 + j + off];
        __syncthreads();
    }
    float mean[R];
    #pragma unroll
    for (int r = 0; r < R; r++) mean[r] = red[r * DD2] * (1.f / 128.f);
    __syncthreads();
    float dv[R];
    #pragma unroll
    for (int r = 0; r < R; r++) { dv[r] = v[r] - mean[r]; red[r * DD2 + j] = dv[r] * dv[r]; }
    __syncthreads();
    for (int off = 64; off > 0; off >>= 1) {
        if (j < off)
            #pragma unroll
            for (int r = 0; r < R; r++) red[r * DD2 + j] += red[r * DD2 + j + off];
        __syncthreads();
    }
    const float* ln1l = ln1 + l * 2 * DD2;
    float lnw = ln1l[j], lnb = ln1l[DD2 + j];
    float xv[R];
    #pragma unroll
    for (int r = 0; r < R; r++) {
        float var = red[r * DD2] * (1.f / 128.f);
        xv[r] = dv[r] * rsqrtf(var + 1e-5f) * lnw + lnb;
        xsp[j * R + r] = xv[r];
    }
    __syncthreads();
    // ---- FF1: thread j -> cols j*4..j*4+3, 8 rows ----
    const float* W1l = W1 + l * DD2 * 512;
    float4 b14 = __ldg((const float4*)&b1[l * 512 + j * 4]);
    unsigned long long f1[4][4];         // [col][rowpair]
    {
        float bb[4] = {b14.x, b14.y, b14.z, b14.w};
        #pragma unroll
        for (int c = 0; c < 4; c++) {
            unsigned long long p;
            PACKF2(p, bb[c], bb[c]);
            f1[c][0] = p; f1[c][1] = p; f1[c][2] = p; f1[c][3] = p;
        }
    }
    #pragma unroll 2
    for (int k = 0; k < DD2; k++) {
        float4 w4 = __ldg((const float4*)&W1l[k * 512 + j * 4]);
        ulonglong2 x0 = *(const ulonglong2*)&xsp[k * R];
        ulonglong2 x1 = *(const ulonglong2*)&xsp[k * R + 4];
        float wc[4] = {w4.x, w4.y, w4.z, w4.w};
        #pragma unroll
        for (int c = 0; c < 4; c++) {
            unsigned long long wd;
            PACKF2(wd, wc[c], wc[c]);
            FMA_F32X2(f1[c][0], wd, x0.x, f1[c][0]);
            FMA_F32X2(f1[c][1], wd, x0.y, f1[c][1]);
            FMA_F32X2(f1[c][2], wd, x1.x, f1[c][2]);
            FMA_F32X2(f1[c][3], wd, x1.y, f1[c][3]);
        }
    }
    #pragma unroll
    for (int c = 0; c < 4; c++) {
        #pragma unroll
        for (int q = 0; q < 4; q++) {
            float lo, hi;
            UNPACKF2(lo, hi, f1[c][q]);
            shf[(j * 4 + c) * R + 2 * q]     = fmaxf(lo, 0.f);
            shf[(j * 4 + c) * R + 2 * q + 1] = fmaxf(hi, 0.f);
        }
    }
    __syncthreads();
    // ---- FF2 ----
    const float* W2l = W2 + l * 512 * DD2;
    float bb2 = b2[l * DD2 + j];
    unsigned long long f2[4];
    {
        unsigned long long p;
        PACKF2(p, bb2, bb2);
        f2[0] = p; f2[1] = p; f2[2] = p; f2[3] = p;
    }
    #pragma unroll 4
    for (int k = 0; k < 512; k++) {
        float w = __ldg(&W2l[k * DD2 + j]);
        unsigned long long wd;
        PACKF2(wd, w, w);
        ulonglong2 y0 = *(const ulonglong2*)&shf[k * R];
        ulonglong2 y1 = *(const ulonglong2*)&shf[k * R + 4];
        FMA_F32X2(f2[0], wd, y0.x, f2[0]);
        FMA_F32X2(f2[1], wd, y0.y, f2[1]);
        FMA_F32X2(f2[2], wd, y1.x, f2[2]);
        FMA_F32X2(f2[3], wd, y1.y, f2[3]);
    }
    float v2[R];
    #pragma unroll
    for (int q = 0; q < 4; q++) UNPACKF2(v2[2 * q], v2[2 * q + 1], f2[q]);
    #pragma unroll
    for (int r = 0; r < R; r++) v2[r] += xv[r];
    // ---- LN2 ----
    #pragma unroll
    for (int r = 0; r < R; r++) red[r * DD2 + j] = v2[r];
    __syncthreads();
    for (int off = 64; off > 0; off >>= 1) {
        if (j < off)
            #pragma unroll
            for (int r = 0; r < R; r++) red[r * DD2 + j] += red[r * DD2 + j + off];
        __syncthreads();
    }
    float mean2[R];
    #pragma unroll
    for (int r = 0; r < R; r++) mean2[r] = red[r * DD2] * (1.f / 128.f);
    __syncthreads();
    float dv2[R];
    #pragma unroll
    for (int r = 0; r < R; r++) { dv2[r] = v2[r] - mean2[r]; red[r * DD2 + j] = dv2[r] * dv2[r]; }
    __syncthreads();
    for (int off = 64; off > 0; off >>= 1) {
        if (j < off)
            #pragma unroll
            for (int r = 0; r < R; r++) red[r * DD2 + j] += red[r * DD2 + j + off];
        __syncthreads();
    }
    const float* ln2l = ln2 + l * 2 * DD2;
    float lnw2 = ln2l[j], lnb2 = ln2l[DD2 + j];
    #pragma unroll
    for (int r = 0; r < R; r++) {
        float var2 = red[r * DD2] * (1.f / 128.f);
        g_xseq[(row0 + r) * DD2 + j] = dv2[r] * rsqrtf(var2 + 1e-5f) * lnw2 + lnb2;
    }
}

// ---------------- final scoring MLP: 4 candidates per block -------------------
__global__ void k_score(const int* __restrict__ tidx,
                        const float* __restrict__ W1, const float* __restrict__ b1,
                        const float* __restrict__ W2, const float* __restrict__ b2,
                        float* __restrict__ out) {
    const int C = 4;
    __shared__ float ftp[FDIM * C];      // [q][cand]
    __shared__ float sh[C][256];
    int g0 = blockIdx.x * C;
    int j = threadIdx.x;                 // 192
    #pragma unroll
    for (int c = 0; c < C; c++) {
        int gc = g0 + c;
        int b = gc / KK;
        float v;
        if (j < DD) {
            v = g_xB[tidx[gc] * DD + j];
        } else {
            int col = j - DD;
            float ssum = 0.f;
            #pragma unroll 10
            for (int t = 0; t < HL; t++) ssum += g_xseq[(b * HL + t) * DD2 + col];
            v = ssum * (1.f / (float)HL);
        }
        ftp[j * C + c] = v;
    }
    if (j < 64) {
        #pragma unroll
        for (int c = 0; c < C; c++) sh[c][192 + j] = 0.f;
    }
    __syncthreads();
    float bj = b1[j];
    unsigned long long a01, a23;
    PACKF2(a01, bj, bj);
    a23 = a01;
    #pragma unroll 8
    for (int q = 0; q < FDIM; q++) {
        float w = __ldg(&W1[q * FDIM + j]);
        unsigned long long wd;
        PACKF2(wd, w, w);
        ulonglong2 x = *(const ulonglong2*)&ftp[q * C];
        FMA_F32X2(a01, wd, x.x, a01);
        FMA_F32X2(a23, wd, x.y, a23);
    }
    float h[4];
    UNPACKF2(h[0], h[1], a01);
    UNPACKF2(h[2], h[3], a23);
    float w2j = W2[j];
    #pragma unroll
    for (int c = 0; c < C; c++) sh[c][j] = fmaxf(h[c], 0.f) * w2j;
    __syncthreads();
    for (int off = 128; off > 0; off >>= 1) {
        if (j < off) {
            #pragma unroll
            for (int c = 0; c < C; c++) sh[c][j] += sh[c][j + off];
        }
        __syncthreads();
    }
    if (j < C) out[g0 + j] = sh[j][0] + b2[0];
}

// ---------------- host launcher -------------------------------------------------
extern "C" void kernel_launch(void* const* d_in, const int* in_sizes, int n_in,
                              void* d_out, int out_size) {
    const float* poi   = (const float*)d_in[0];
    const float* qemb  = (const float*)d_in[1];
    const float* gateW = (const float*)d_in[2];
    const float* gateb = (const float*)d_in[3];
    const float* gnn_rel = (const float*)d_in[4];
    const float* gnn_W   = (const float*)d_in[5];
    const float* gnn_b   = (const float*)d_in[6];
    const float* gte  = (const float*)d_in[7];
    const float* glW  = (const float*)d_in[8];
    const float* glb  = (const float*)d_in[9];
    const float* Wqkv = (const float*)d_in[10];
    const float* Wo   = (const float*)d_in[11];
    const float* ln1  = (const float*)d_in[12];
    const float *W1, *b1, *W2, *b2, *ln2;
    if (in_sizes[13] == 2 * 2 * DD2) {       // dict order: ln2 right after ln1
        ln2 = (const float*)d_in[13];
        W1  = (const float*)d_in[14];
        b1  = (const float*)d_in[15];
        W2  = (const float*)d_in[16];
        b2  = (const float*)d_in[17];
    } else {                                 // signature order
        W1  = (const float*)d_in[13];
        b1  = (const float*)d_in[14];
        W2  = (const float*)d_in[15];
        b2  = (const float*)d_in[16];
        ln2 = (const float*)d_in[17];
    }
    const float* mW1 = (const float*)d_in[18];
    const float* mb1 = (const float*)d_in[19];
    const float* mW2 = (const float*)d_in[20];
    const float* mb2 = (const float*)d_in[21];
    const float* hte = (const float*)d_in[22];
    const int* esrc  = (const int*)d_in[23];
    const int* edst  = (const int*)d_in[24];
    const int* etyp  = (const int*)d_in[25];
    const int* ridx  = (const int*)d_in[27];
    const int* tidx  = (const int*)d_in[28];
    const int* hpoi  = (const int*)d_in[29];
    const int* gtime = (const int*)d_in[30];
    float* out = (float*)d_out;

    k_zero<<<dim3((NN + 255) / 256, SS), 256>>>();
    k_count<<<dim3((EE + 255) / 256, SS), 256>>>(esrc, edst);
    k_offsets<<<dim3((NN + 255) / 256, SS), 256>>>();
    k_scatter<<<dim3((EE + 255) / 256, SS), 256>>>(esrc, edst, etyp);
    k_relsum_init0<<<dim3(NN * DD / 256 + 1, SS), 256>>>(
        gnn_rel, poi, qemb, ridx, gte, gtime, glW, glb);

    for (int s = 0; s < SS; s++) {
        k_layer<<<NN / 16, 256>>>(s, 0, 0, gnn_W, gnn_b, gateW, gateb, poi);
        int mode = (s < SS - 1) ? 2 : 1;
        k_layer<<<NN / 16, 256>>>(s, 1, mode, gnn_W + 2 * DD * DD, gnn_b + DD,
                                  gateW, gateb, poi);
    }

    for (int l = 0; l < 2; l++) {
        k_qkv<<<BB * HL / 2, 3 * DD2>>>(Wqkv, l, l == 0 ? 1 : 0, hpoi, hte);
        k_att<<<dim3(BB, 2), 256>>>();
        k_ffn<<<BB * HL / 8, DD2>>>(Wo, ln1, W1, b1, W2, b2, ln2, l);
    }
    k_score<<<BB * KK / 4, FDIM>>>(tidx, mW1, mb1, mW2, mb2, out);
}